// round 1
// baseline (speedup 1.0000x reference)
#include <cuda_runtime.h>
#include <math.h>

#define Bz 32
#define Tz 512
#define Iz 512
#define Uz 1024
#define Gz 4096     // 4*Uz
#define NCTA 128
#define HPAD 516    // h_s row pad: 516 % 32 == 4 -> conflict-free LDS.128

// Scratch (device globals: allocation-free rule)
__device__ float g_xp[(size_t)Tz * Bz * Gz];   // [T][B][4U] precomputed input proj
__device__ float g_h[2][Bz * Uz];              // double-buffered hidden state
__device__ unsigned g_count;                   // grid barrier counter

// ---------------------------------------------------------------------------
// Kernel 0: reset barrier counter + zero h buffers (per graph replay)
// ---------------------------------------------------------------------------
__global__ void reset_kernel() {
  int i = blockIdx.x * blockDim.x + threadIdx.x;
  if (i == 0) g_count = 0u;
  if (i < 2 * Bz * Uz) ((float*)g_h)[i] = 0.0f;
}

// ---------------------------------------------------------------------------
// Kernel 1: x_proj = data @ Wx + b   (M=16384, N=4096, K=512) classic SGEMM
// Output layout: g_xp[t][b][n]
// ---------------------------------------------------------------------------
__global__ void __launch_bounds__(256) xproj_kernel(
    const float* __restrict__ A, const float* __restrict__ W,
    const float* __restrict__ bias) {
  __shared__ float As[8][128];   // transposed A tile
  __shared__ float Bs[8][128];
  const int tid = threadIdx.x;
  const int m0 = blockIdx.y * 128;
  const int n0 = blockIdx.x * 128;
  const int arow = tid >> 1;
  const int acol = (tid & 1) << 2;
  const int brow = tid >> 5;
  const int bcol = (tid & 31) << 2;
  const int tr = (tid >> 4) << 3;
  const int tc = (tid & 15) << 3;
  float acc[8][8];
#pragma unroll
  for (int i = 0; i < 8; i++)
#pragma unroll
    for (int j = 0; j < 8; j++) acc[i][j] = 0.0f;

  for (int k0 = 0; k0 < Iz; k0 += 8) {
    float4 av = *(const float4*)(A + (size_t)(m0 + arow) * Iz + k0 + acol);
    As[acol + 0][arow] = av.x;
    As[acol + 1][arow] = av.y;
    As[acol + 2][arow] = av.z;
    As[acol + 3][arow] = av.w;
    *(float4*)(&Bs[brow][bcol]) =
        *(const float4*)(W + (size_t)(k0 + brow) * Gz + n0 + bcol);
    __syncthreads();
#pragma unroll
    for (int kk = 0; kk < 8; kk++) {
      float4 a0 = *(const float4*)(&As[kk][tr]);
      float4 a1 = *(const float4*)(&As[kk][tr + 4]);
      float4 b0 = *(const float4*)(&Bs[kk][tc]);
      float4 b1 = *(const float4*)(&Bs[kk][tc + 4]);
      float ar[8] = {a0.x, a0.y, a0.z, a0.w, a1.x, a1.y, a1.z, a1.w};
      float br[8] = {b0.x, b0.y, b0.z, b0.w, b1.x, b1.y, b1.z, b1.w};
#pragma unroll
      for (int i = 0; i < 8; i++)
#pragma unroll
        for (int j = 0; j < 8; j++) acc[i][j] += ar[i] * br[j];
    }
    __syncthreads();
  }
#pragma unroll
  for (int i = 0; i < 8; i++) {
    int m = m0 + tr + i;          // m = b*512 + t  (data is [B,T,I])
    int t = m & (Tz - 1);
    int b = m >> 9;
    float* o = &g_xp[((size_t)t * Bz + b) * Gz + n0 + tc];
#pragma unroll
    for (int j = 0; j < 8; j++) o[j] = acc[i][j] + bias[n0 + tc + j];
  }
}

// ---------------------------------------------------------------------------
// Kernel 2: persistent LSTM recurrence.
// 128 CTAs, each owns 8 hidden units (= 32 gate columns: 4 gates x 8 units).
// Wh slice [1024 x 32] fp32 lives in SMEM for all 512 steps.
// Grid-wide epoch barrier per step; h double-buffered in global memory.
// ---------------------------------------------------------------------------
__global__ void __launch_bounds__(256, 1) lstm_kernel(
    const float* __restrict__ Wh, float* __restrict__ out) {
  extern __shared__ float sm[];
  float* Wh_s = sm;                    // [1024][32]  (col c = gate*8 + unit)
  float* h_s = sm + Uz * 32;           // [32][HPAD]  staged h chunk (512 k)
  float* gates_s = h_s + Bz * HPAD;    // [32][32]
  float* c_s = gates_s + Bz * 32;      // [256] cell state (b*8+u)
  const int tid = threadIdx.x;
  const int u0 = blockIdx.x * 8;

  // Load Wh slice: Wh_s[k][c] = Wh[k][ (c>>3)*1024 + u0 + (c&7) ]
  for (int idx = tid; idx < Uz * 32; idx += 256) {
    int k = idx >> 5, c = idx & 31;
    Wh_s[idx] = Wh[(size_t)k * Gz + (c >> 3) * Uz + u0 + (c & 7)];
  }
  c_s[tid] = 0.0f;
  __syncthreads();

  const int tn = tid & 7;              // column group (4 cols each)
  const int tb = tid >> 3;             // batch row
  const int colbase = tn << 2;
  const int gcol = (tn >> 1) * Uz + u0 + (tn & 1) * 4;  // global gate col base
  const float* hrow = &h_s[tb * HPAD];
  const float* wrow = &Wh_s[colbase];

  for (int t = 0; t < Tz; t++) {
    const int rb = t & 1;
    const float* hg = g_h[rb];
    float4 acc = *(const float4*)(&g_xp[((size_t)t * Bz + tb) * Gz + gcol]);

    for (int k0 = 0; k0 < Uz; k0 += 512) {
      // Stage h[:, k0:k0+512] into SMEM. __ldcg: L1 holds stale lines from
      // earlier steps (same addresses, other SMs wrote since) -> must read L2.
      for (int idx = tid; idx < 4096; idx += 256) {
        int b = idx >> 7;
        int kk = (idx & 127) << 2;
        *(float4*)(&h_s[b * HPAD + kk]) =
            __ldcg((const float4*)(&hg[b * Uz + k0 + kk]));
      }
      __syncthreads();
      const float* wr = wrow + k0 * 32;
#pragma unroll 8
      for (int kk = 0; kk < 512; kk += 4) {
        float4 hv = *(const float4*)(hrow + kk);
        float4 w0 = *(const float4*)(wr + (kk + 0) * 32);
        float4 w1 = *(const float4*)(wr + (kk + 1) * 32);
        float4 w2 = *(const float4*)(wr + (kk + 2) * 32);
        float4 w3 = *(const float4*)(wr + (kk + 3) * 32);
        acc.x += hv.x * w0.x + hv.y * w1.x + hv.z * w2.x + hv.w * w3.x;
        acc.y += hv.x * w0.y + hv.y * w1.y + hv.z * w2.y + hv.w * w3.y;
        acc.z += hv.x * w0.z + hv.y * w1.z + hv.z * w2.z + hv.w * w3.z;
        acc.w += hv.x * w0.w + hv.y * w1.w + hv.z * w2.w + hv.w * w3.w;
      }
      __syncthreads();
    }

    *(float4*)(&gates_s[tb * 32 + colbase]) = acc;
    __syncthreads();

    // Nonlinearity: thread -> (b = tid>>3, u = tid&7), exactly 256 cells.
    {
      const float* gr = &gates_s[tb * 32];
      float xi = gr[tn], xf = gr[8 + tn], xg = gr[16 + tn], xo = gr[24 + tn];
      float iv = 1.0f / (1.0f + expf(-xi));
      float fv = 1.0f / (1.0f + expf(-xf));
      float gv = tanhf(xg);
      float ov = 1.0f / (1.0f + expf(-xo));
      float cn = fv * c_s[tid] + iv * gv;
      c_s[tid] = cn;
      float hn = ov * tanhf(cn);
      g_h[1 - rb][tb * Uz + u0 + tn] = hn;
      out[((size_t)tb * Tz + t) * Uz + u0 + tn] = hn;
    }

    // Grid-wide epoch barrier (all 128 CTAs guaranteed resident).
    __syncthreads();
    if (tid == 0) {
      __threadfence();                       // release our h writes
      atomicAdd(&g_count, 1u);
      unsigned tgt = (unsigned)(t + 1) * (unsigned)NCTA;
      volatile unsigned* vc = &g_count;
      while (*vc < tgt) {
      }
      __threadfence();                       // acquire others' h writes
    }
    __syncthreads();
  }
}

// ---------------------------------------------------------------------------
extern "C" void kernel_launch(void* const* d_in, const int* in_sizes, int n_in,
                              void* d_out, int out_size) {
  const float* data = (const float*)d_in[0];  // [32,512,512]
  const float* Wx = (const float*)d_in[1];    // [512,4096]
  const float* Wh = (const float*)d_in[2];    // [1024,4096]
  const float* bias = (const float*)d_in[3];  // [4096]
  float* out = (float*)d_out;                 // [32,512,1024]

  const int smem_bytes = (Uz * 32 + Bz * HPAD + Bz * 32 + 256) * sizeof(float);
  cudaFuncSetAttribute(lstm_kernel, cudaFuncAttributeMaxDynamicSharedMemorySize,
                       smem_bytes);

  reset_kernel<<<(2 * Bz * Uz + 255) / 256, 256>>>();

  dim3 gg(Gz / 128, (Bz * Tz) / 128);
  xproj_kernel<<<gg, 256>>>(data, Wx, bias);

  lstm_kernel<<<NCTA, 256, smem_bytes>>>(Wh, out);
}

// round 2
// speedup vs baseline: 1.4651x; 1.4651x over previous
#include <cuda_runtime.h>
#include <math.h>

#define Bz 32
#define Tz 512
#define Iz 512
#define Uz 1024
#define Gz 4096     // 4*Uz
#define NCTA 128
#define HPAD 516    // h_s row pad (float count): 516 % 32 == 4 -> bank-shifted rows

// Scratch (device globals: allocation-free rule)
__device__ float g_xp[(size_t)Tz * Bz * Gz];   // [T][B][4U] input projections
__device__ float g_h[2][Bz * Uz];              // double-buffered hidden state
__device__ unsigned g_count;                   // grid barrier counter

// ---------------------------------------------------------------------------
// packed fp32x2 helpers (sm_100+): one instruction, two fp32 FMAs
// ---------------------------------------------------------------------------
__device__ __forceinline__ unsigned long long ffma2(unsigned long long a,
                                                    unsigned long long b,
                                                    unsigned long long c) {
  unsigned long long d;
  asm("fma.rn.f32x2 %0, %1, %2, %3;" : "=l"(d) : "l"(a), "l"(b), "l"(c));
  return d;
}
__device__ __forceinline__ unsigned long long fadd2(unsigned long long a,
                                                    unsigned long long b) {
  unsigned long long d;
  asm("add.rn.f32x2 %0, %1, %2;" : "=l"(d) : "l"(a), "l"(b));
  return d;
}
__device__ __forceinline__ unsigned long long pack2(float x) {
  unsigned long long r;
  unsigned u = __float_as_uint(x);
  asm("mov.b64 %0, {%1, %1};" : "=l"(r) : "r"(u));
  return r;
}
__device__ __forceinline__ float f2lo(unsigned long long v) {
  return __uint_as_float((unsigned)v);
}
__device__ __forceinline__ float f2hi(unsigned long long v) {
  return __uint_as_float((unsigned)(v >> 32));
}

// ---------------------------------------------------------------------------
// Kernel 1: x_proj = data @ Wx + b   (M=16384, N=4096, K=512)
// 128x128 tile / 256 threads, 8x8 per thread, f32x2 over column pairs.
// Block (0,0) also resets g_h / g_count (runs before lstm in-stream).
// ---------------------------------------------------------------------------
__global__ void __launch_bounds__(256) xproj_kernel(
    const float* __restrict__ A, const float* __restrict__ W,
    const float* __restrict__ bias) {
  if (blockIdx.x == 0 && blockIdx.y == 0) {
    for (int i = threadIdx.x; i < 2 * Bz * Uz; i += 256) ((float*)g_h)[i] = 0.f;
    if (threadIdx.x == 0) g_count = 0u;
  }
  __shared__ float As[8][128];  // transposed A tile
  __shared__ float Bs[8][128];
  const int tid = threadIdx.x;
  const int m0 = blockIdx.y * 128;
  const int n0 = blockIdx.x * 128;
  const int arow = tid >> 1;
  const int acol = (tid & 1) << 2;
  const int brow = tid >> 5;
  const int bcol = (tid & 31) << 2;
  const int tr = (tid >> 4) << 3;
  const int tc = (tid & 15) << 3;

  unsigned long long accp[8][4];
#pragma unroll
  for (int i = 0; i < 8; i++)
#pragma unroll
    for (int j = 0; j < 4; j++) accp[i][j] = 0ull;

  float4 av = *(const float4*)(A + (size_t)(m0 + arow) * Iz + acol);
  float4 bv = *(const float4*)(W + (size_t)brow * Gz + n0 + bcol);

  for (int k0 = 0; k0 < Iz; k0 += 8) {
    As[acol + 0][arow] = av.x;
    As[acol + 1][arow] = av.y;
    As[acol + 2][arow] = av.z;
    As[acol + 3][arow] = av.w;
    *(float4*)(&Bs[brow][bcol]) = bv;
    __syncthreads();
    if (k0 + 8 < Iz) {
      av = *(const float4*)(A + (size_t)(m0 + arow) * Iz + k0 + 8 + acol);
      bv = *(const float4*)(W + (size_t)(k0 + 8 + brow) * Gz + n0 + bcol);
    }
#pragma unroll
    for (int kk = 0; kk < 8; kk++) {
      float4 a0 = *(const float4*)(&As[kk][tr]);
      float4 a1 = *(const float4*)(&As[kk][tr + 4]);
      ulonglong2 b0 = *(const ulonglong2*)(&Bs[kk][tc]);
      ulonglong2 b1 = *(const ulonglong2*)(&Bs[kk][tc + 4]);
      float ar[8] = {a0.x, a0.y, a0.z, a0.w, a1.x, a1.y, a1.z, a1.w};
#pragma unroll
      for (int i = 0; i < 8; i++) {
        unsigned long long aa = pack2(ar[i]);
        accp[i][0] = ffma2(aa, b0.x, accp[i][0]);
        accp[i][1] = ffma2(aa, b0.y, accp[i][1]);
        accp[i][2] = ffma2(aa, b1.x, accp[i][2]);
        accp[i][3] = ffma2(aa, b1.y, accp[i][3]);
      }
    }
    __syncthreads();
  }
#pragma unroll
  for (int i = 0; i < 8; i++) {
    int m = m0 + tr + i;  // m = b*512 + t (data is [B,T,I])
    int t = m & (Tz - 1);
    int b = m >> 9;
    float* o = &g_xp[((size_t)t * Bz + b) * Gz + n0 + tc];
#pragma unroll
    for (int j = 0; j < 4; j++) {
      o[2 * j + 0] = f2lo(accp[i][j]) + bias[n0 + tc + 2 * j + 0];
      o[2 * j + 1] = f2hi(accp[i][j]) + bias[n0 + tc + 2 * j + 1];
    }
  }
}

// ---------------------------------------------------------------------------
// Kernel 2: persistent LSTM recurrence, f32x2 datapath.
// 128 CTAs x 256 threads. CTA owns 8 hidden units = 32 gate cols.
// Thread = (cg 0..7: 4 cols) x (rp 0..15: rows 2rp,2rp+1) x (kh 0..1: K half).
// Wh slice [1024 x 32] fp32 in SMEM, (kpair, colhalf, colpair, parity) layout
// so the 8 cg LDS.128 chunks land on distinct banks.
// ---------------------------------------------------------------------------
__global__ void __launch_bounds__(256, 1) lstm_kernel(
    const float* __restrict__ Wh, float* __restrict__ out) {
  extern __shared__ float sm[];
  float* Wh_s = sm;                     // 32768 floats
  float* h_s = Wh_s + Uz * 32;          // [32][HPAD] staged 512-k chunk
  float* gates_s = h_s + Bz * HPAD;     // [32][32]
  float* c_s = gates_s + Bz * 32;       // [256]
  unsigned long long* red_s = (unsigned long long*)(c_s + 256);  // [128][8]
  const int tid = threadIdx.x;
  const int u0 = blockIdx.x * 8;

  // Wh_s[(k>>1)*64 + ((c>>1)&1)*32 + (c>>2)*4 + (c&1)*2 + (k&1)]
  //   where col c = gate*8 + unit
  for (int idx = tid; idx < Uz * 32; idx += 256) {
    int k = idx >> 5, c = idx & 31;
    int dst = (k >> 1) * 64 + ((c >> 1) & 1) * 32 + (c >> 2) * 4 +
              ((c & 1) << 1) + (k & 1);
    Wh_s[dst] = Wh[(size_t)k * Gz + (c >> 3) * Uz + u0 + (c & 7)];
  }
  c_s[tid] = 0.0f;
  __syncthreads();

  const int cg = tid & 7;
  const int rp = (tid >> 3) & 15;
  const int kh = tid >> 7;
  const int r0 = rp * 2, r1 = r0 + 1;
  const float* hrA = h_s + r0 * HPAD;
  const float* hrB = h_s + r1 * HPAD;
  const int khbase = kh << 8;  // 0 or 256 (k offset within staged chunk)
  const int b_nl = tid >> 3, un = tid & 7;  // nonlinearity mapping

  float4 buf[16];

  for (int t = 0; t < Tz; t++) {
    const int rb = t & 1;
    const float* hg = g_h[rb];
    unsigned long long acc[2][4];
#pragma unroll
    for (int i = 0; i < 2; i++)
#pragma unroll
      for (int j = 0; j < 4; j++) acc[i][j] = 0ull;

    // ---- stage chunk 0 (k 0..511). __ldcg: L1 lines are stale across steps.
#pragma unroll
    for (int i = 0; i < 16; i++) {
      int idx = tid + 256 * i;
      int b = idx >> 7, kk = (idx & 127) << 2;
      buf[i] = __ldcg((const float4*)(&hg[b * Uz + kk]));
    }
#pragma unroll
    for (int i = 0; i < 16; i++) {
      int idx = tid + 256 * i;
      int b = idx >> 7, kk = (idx & 127) << 2;
      *(float4*)(&h_s[b * HPAD + kk]) = buf[i];
    }
    __syncthreads();
    // prefetch chunk 1 into registers (latency hidden under chunk-0 compute)
#pragma unroll
    for (int i = 0; i < 16; i++) {
      int idx = tid + 256 * i;
      int b = idx >> 7, kk = (idx & 127) << 2;
      buf[i] = __ldcg((const float4*)(&hg[b * Uz + 512 + kk]));
    }

    // ---- compute over both chunks
#pragma unroll 1
    for (int ch = 0; ch < 2; ch++) {
      const float* wch = Wh_s + (ch * 512 >> 1) * 64;
#pragma unroll 4
      for (int kk = khbase; kk < khbase + 256; kk += 4) {
        ulonglong2 hA = *(const ulonglong2*)(hrA + kk);
        ulonglong2 hB = *(const ulonglong2*)(hrB + kk);
        const float* wp = wch + (kk >> 1) * 64 + cg * 4;
        ulonglong2 w0a = *(const ulonglong2*)(wp);
        ulonglong2 w1a = *(const ulonglong2*)(wp + 32);
        ulonglong2 w0b = *(const ulonglong2*)(wp + 64);
        ulonglong2 w1b = *(const ulonglong2*)(wp + 96);
        acc[0][0] = ffma2(hA.x, w0a.x, acc[0][0]);
        acc[0][1] = ffma2(hA.x, w0a.y, acc[0][1]);
        acc[0][2] = ffma2(hA.x, w1a.x, acc[0][2]);
        acc[0][3] = ffma2(hA.x, w1a.y, acc[0][3]);
        acc[1][0] = ffma2(hB.x, w0a.x, acc[1][0]);
        acc[1][1] = ffma2(hB.x, w0a.y, acc[1][1]);
        acc[1][2] = ffma2(hB.x, w1a.x, acc[1][2]);
        acc[1][3] = ffma2(hB.x, w1a.y, acc[1][3]);
        acc[0][0] = ffma2(hA.y, w0b.x, acc[0][0]);
        acc[0][1] = ffma2(hA.y, w0b.y, acc[0][1]);
        acc[0][2] = ffma2(hA.y, w1b.x, acc[0][2]);
        acc[0][3] = ffma2(hA.y, w1b.y, acc[0][3]);
        acc[1][0] = ffma2(hB.y, w0b.x, acc[1][0]);
        acc[1][1] = ffma2(hB.y, w0b.y, acc[1][1]);
        acc[1][2] = ffma2(hB.y, w1b.x, acc[1][2]);
        acc[1][3] = ffma2(hB.y, w1b.y, acc[1][3]);
      }
      if (ch == 0) {
        __syncthreads();  // chunk-0 compute done; safe to overwrite h_s
#pragma unroll
        for (int i = 0; i < 16; i++) {
          int idx = tid + 256 * i;
          int b = idx >> 7, kk = (idx & 127) << 2;
          *(float4*)(&h_s[b * HPAD + kk]) = buf[i];
        }
        __syncthreads();
      }
    }

    // ---- reduce the two K-halves, add xp, write gates
    if (kh == 1) {
      unsigned long long* rs = &red_s[(tid - 128) * 8];
#pragma unroll
      for (int i = 0; i < 2; i++)
#pragma unroll
        for (int j = 0; j < 4; j++) rs[i * 4 + j] = acc[i][j];
    }
    __syncthreads();
    if (kh == 0) {
      const unsigned long long* rs = &red_s[tid * 8];
      int gcb = (cg >> 1) * Uz + u0 + ((cg & 1) << 2);
      float4 xpA = *(const float4*)(&g_xp[((size_t)t * Bz + r0) * Gz + gcb]);
      float4 xpB = *(const float4*)(&g_xp[((size_t)t * Bz + r1) * Gz + gcb]);
      float xa[4] = {xpA.x, xpA.y, xpA.z, xpA.w};
      float xb[4] = {xpB.x, xpB.y, xpB.z, xpB.w};
#pragma unroll
      for (int j = 0; j < 4; j++) {
        unsigned long long vA = fadd2(acc[0][j], rs[j]);
        unsigned long long vB = fadd2(acc[1][j], rs[4 + j]);
        gates_s[r0 * 32 + cg * 4 + j] = xa[j] + f2lo(vA) + f2hi(vA);
        gates_s[r1 * 32 + cg * 4 + j] = xb[j] + f2lo(vB) + f2hi(vB);
      }
    }
    __syncthreads();

    // ---- nonlinearity: thread -> (b = tid>>3, u = tid&7)
    {
      const float* gr = &gates_s[b_nl * 32];
      float xi = gr[un], xf = gr[8 + un], xg = gr[16 + un], xo = gr[24 + un];
      float iv = 1.0f / (1.0f + expf(-xi));
      float fv = 1.0f / (1.0f + expf(-xf));
      float gv = tanhf(xg);
      float ov = 1.0f / (1.0f + expf(-xo));
      float cn = fv * c_s[tid] + iv * gv;
      c_s[tid] = cn;
      float hn = ov * tanhf(cn);
      g_h[1 - rb][b_nl * Uz + u0 + un] = hn;
      out[((size_t)b_nl * Tz + t) * Uz + u0 + un] = hn;
    }

    // ---- grid-wide epoch barrier (128 CTAs all resident)
    __syncthreads();
    if (tid == 0) {
      __threadfence();
      atomicAdd(&g_count, 1u);
      unsigned tgt = (unsigned)(t + 1) * (unsigned)NCTA;
      volatile unsigned* vc = &g_count;
      while (*vc < tgt) {
      }
      __threadfence();
    }
    __syncthreads();
  }
}

// ---------------------------------------------------------------------------
extern "C" void kernel_launch(void* const* d_in, const int* in_sizes, int n_in,
                              void* d_out, int out_size) {
  const float* data = (const float*)d_in[0];  // [32,512,512]
  const float* Wx = (const float*)d_in[1];    // [512,4096]
  const float* Wh = (const float*)d_in[2];    // [1024,4096]
  const float* bias = (const float*)d_in[3];  // [4096]
  float* out = (float*)d_out;                 // [32,512,1024]

  const int smem_bytes =
      (Uz * 32 + Bz * HPAD + Bz * 32 + 256) * (int)sizeof(float) +
      128 * 8 * (int)sizeof(unsigned long long);
  cudaFuncSetAttribute(lstm_kernel, cudaFuncAttributeMaxDynamicSharedMemorySize,
                       smem_bytes);

  dim3 gg(Gz / 128, (Bz * Tz) / 128);
  xproj_kernel<<<gg, 256>>>(data, Wx, bias);

  lstm_kernel<<<NCTA, 256, smem_bytes>>>(Wh, out);
}

// round 4
// speedup vs baseline: 1.4874x; 1.0152x over previous
#include <cuda_runtime.h>
#include <math.h>

#define Bz 32
#define Tz 512
#define Iz 512
#define Uz 1024
#define Gz 4096     // 4*Uz
#define NCTA 128
#define NTH 512
#define HPAD 516    // h_s row pad (floats): rows land on shifted banks

// Scratch (device globals: allocation-free rule)
__device__ float g_xp[(size_t)Tz * Bz * Gz];   // [T][B][4U] input projections
__device__ float g_h[2][Bz * Uz];              // double-buffered hidden state
__device__ unsigned g_count;                   // grid barrier counter

typedef unsigned long long ull;

// ---------------------------------------------------------------------------
// packed fp32x2 helpers (sm_100+): one instruction, two fp32 FMAs
// ---------------------------------------------------------------------------
__device__ __forceinline__ ull ffma2(ull a, ull b, ull c) {
  ull d;
  asm("fma.rn.f32x2 %0, %1, %2, %3;" : "=l"(d) : "l"(a), "l"(b), "l"(c));
  return d;
}
__device__ __forceinline__ ull fadd2(ull a, ull b) {
  ull d;
  asm("add.rn.f32x2 %0, %1, %2;" : "=l"(d) : "l"(a), "l"(b));
  return d;
}
__device__ __forceinline__ ull pack2(float x) {
  ull r;
  unsigned u = __float_as_uint(x);
  asm("mov.b64 %0, {%1, %1};" : "=l"(r) : "r"(u));
  return r;
}
__device__ __forceinline__ float f2lo(ull v) {
  return __uint_as_float((unsigned)v);
}
__device__ __forceinline__ float f2hi(ull v) {
  return __uint_as_float((unsigned)(v >> 32));
}
__device__ __forceinline__ float sigm_f(float x) {
  return 1.0f / (1.0f + __expf(-x));
}
__device__ __forceinline__ float tanh_f(float x) {
  return 2.0f / (1.0f + __expf(-2.0f * x)) - 1.0f;
}

// ---------------------------------------------------------------------------
// Kernel 1: x_proj = data @ Wx + b   (M=16384, N=4096, K=512)
// 128x128 tile / 256 threads, 8x8 per thread, f32x2 over column pairs.
// Block (0,0) also resets g_h / g_count (runs before lstm in-stream).
// ---------------------------------------------------------------------------
__global__ void __launch_bounds__(256) xproj_kernel(
    const float* __restrict__ A, const float* __restrict__ W,
    const float* __restrict__ bias) {
  if (blockIdx.x == 0 && blockIdx.y == 0) {
    for (int i = threadIdx.x; i < 2 * Bz * Uz; i += 256) ((float*)g_h)[i] = 0.f;
    if (threadIdx.x == 0) g_count = 0u;
  }
  __shared__ float As[8][128];  // transposed A tile
  __shared__ float Bs[8][128];
  const int tid = threadIdx.x;
  const int m0 = blockIdx.y * 128;
  const int n0 = blockIdx.x * 128;
  const int arow = tid >> 1;
  const int acol = (tid & 1) << 2;
  const int brow = tid >> 5;
  const int bcol = (tid & 31) << 2;
  const int tr = (tid >> 4) << 3;
  const int tc = (tid & 15) << 3;

  ull accp[8][4];
#pragma unroll
  for (int i = 0; i < 8; i++)
#pragma unroll
    for (int j = 0; j < 4; j++) accp[i][j] = 0ull;

  float4 av = *(const float4*)(A + (size_t)(m0 + arow) * Iz + acol);
  float4 bv = *(const float4*)(W + (size_t)brow * Gz + n0 + bcol);

  for (int k0 = 0; k0 < Iz; k0 += 8) {
    As[acol + 0][arow] = av.x;
    As[acol + 1][arow] = av.y;
    As[acol + 2][arow] = av.z;
    As[acol + 3][arow] = av.w;
    *(float4*)(&Bs[brow][bcol]) = bv;
    __syncthreads();
    if (k0 + 8 < Iz) {
      av = *(const float4*)(A + (size_t)(m0 + arow) * Iz + k0 + 8 + acol);
      bv = *(const float4*)(W + (size_t)(k0 + 8 + brow) * Gz + n0 + bcol);
    }
#pragma unroll
    for (int kk = 0; kk < 8; kk++) {
      float4 a0 = *(const float4*)(&As[kk][tr]);
      float4 a1 = *(const float4*)(&As[kk][tr + 4]);
      ulonglong2 b0 = *(const ulonglong2*)(&Bs[kk][tc]);
      ulonglong2 b1 = *(const ulonglong2*)(&Bs[kk][tc + 4]);
      float ar[8] = {a0.x, a0.y, a0.z, a0.w, a1.x, a1.y, a1.z, a1.w};
#pragma unroll
      for (int i = 0; i < 8; i++) {
        ull aa = pack2(ar[i]);
        accp[i][0] = ffma2(aa, b0.x, accp[i][0]);
        accp[i][1] = ffma2(aa, b0.y, accp[i][1]);
        accp[i][2] = ffma2(aa, b1.x, accp[i][2]);
        accp[i][3] = ffma2(aa, b1.y, accp[i][3]);
      }
    }
    __syncthreads();
  }
#pragma unroll
  for (int i = 0; i < 8; i++) {
    int m = m0 + tr + i;  // m = b*512 + t (data is [B,T,I])
    int t = m & (Tz - 1);
    int b = m >> 9;
    float* o = &g_xp[((size_t)t * Bz + b) * Gz + n0 + tc];
#pragma unroll
    for (int j = 0; j < 4; j++) {
      o[2 * j + 0] = f2lo(accp[i][j]) + bias[n0 + tc + 2 * j + 0];
      o[2 * j + 1] = f2hi(accp[i][j]) + bias[n0 + tc + 2 * j + 1];
    }
  }
}

// ---------------------------------------------------------------------------
// Kernel 2: persistent LSTM recurrence, f32x2 datapath, 512 threads.
// 128 CTAs; CTA owns 8 hidden units = 32 gate cols, 32 batch rows, K=1024.
// Thread = cg (tid&7: 4 cols) x rg ((tid>>3)&15: rows 2rg,2rg+1)
//          x kh (tid>>7: K quarter, 128 k per chunk-half).
// Wh slice [1024 x 32] fp32 in SMEM, layout per k-pair block of 64 floats:
//   dst = kpair*64 + ((c>>1)&1)*32 + (c>>2)*4 + (c&1)*2 + (k&1)
// -> the 8 cg 16B chunks cover all 32 banks exactly once (conflict-free).
// ---------------------------------------------------------------------------
__global__ void __launch_bounds__(NTH, 1) lstm_kernel(
    const float* __restrict__ Wh, float* __restrict__ out) {
  extern __shared__ float sm[];
  float* Wh_s = sm;                     // 32768 floats
  float* h_s = Wh_s + Uz * 32;          // [32][HPAD] staged 512-k chunk
  float* gates_s = h_s + Bz * HPAD;     // [32][32]
  float* c_s = gates_s + Bz * 32;       // [256]
  ull* red_s = (ull*)(c_s + 256);       // [384][8] partials from kh=1,2,3
  const int tid = threadIdx.x;
  const int u0 = blockIdx.x * 8;

  for (int idx = tid; idx < Uz * 32; idx += NTH) {
    int k = idx >> 5, c = idx & 31;
    int dst = (k >> 1) * 64 + ((c >> 1) & 1) * 32 + (c >> 2) * 4 +
              ((c & 1) << 1) + (k & 1);
    Wh_s[dst] = Wh[(size_t)k * Gz + (c >> 3) * Uz + u0 + (c & 7)];
  }
  if (tid < 256) c_s[tid] = 0.0f;
  __syncthreads();

  const int cg = tid & 7;
  const int rg = (tid >> 3) & 15;
  const int kh = tid >> 7;              // 0..3
  const int r0 = rg * 2, r1 = r0 + 1;
  const float* hrA = h_s + r0 * HPAD;
  const float* hrB = h_s + r1 * HPAD;
  const int khbase = kh << 7;           // k offset within each 512-chunk
  const int b_nl = tid >> 3, un = tid & 7;  // nonlinearity mapping (tid<256)
  const int gcb = (cg >> 1) * Uz + u0 + ((cg & 1) << 2);

  float4 buf[8];

  for (int t = 0; t < Tz; t++) {
    const int rb = t & 1;
    const float* hg = g_h[rb];
    ull acc[2][4];
#pragma unroll
    for (int i = 0; i < 2; i++)
#pragma unroll
      for (int j = 0; j < 4; j++) acc[i][j] = 0ull;

    // xp prefetch (independent of h; used at reduce time by kh==0)
    float4 xpA, xpB;
    if (kh == 0) {
      xpA = *(const float4*)(&g_xp[((size_t)t * Bz + r0) * Gz + gcb]);
      xpB = *(const float4*)(&g_xp[((size_t)t * Bz + r1) * Gz + gcb]);
    }

    // ---- stage chunk 0 (k 0..511). __ldcg: L1 lines are stale across steps.
#pragma unroll
    for (int i = 0; i < 8; i++) {
      int idx = tid + NTH * i;
      int b = idx >> 7, kk = (idx & 127) << 2;
      buf[i] = __ldcg((const float4*)(&hg[b * Uz + kk]));
    }
#pragma unroll
    for (int i = 0; i < 8; i++) {
      int idx = tid + NTH * i;
      int b = idx >> 7, kk = (idx & 127) << 2;
      *(float4*)(&h_s[b * HPAD + kk]) = buf[i];
    }
    __syncthreads();
    // prefetch chunk 1 into registers (latency hidden under chunk-0 compute)
#pragma unroll
    for (int i = 0; i < 8; i++) {
      int idx = tid + NTH * i;
      int b = idx >> 7, kk = (idx & 127) << 2;
      buf[i] = __ldcg((const float4*)(&hg[b * Uz + 512 + kk]));
    }

    // ---- compute over both chunks
#pragma unroll 1
    for (int ch = 0; ch < 2; ch++) {
      const float* wch = Wh_s + ch * 256 * 64;
#pragma unroll 2
      for (int kk = khbase; kk < khbase + 128; kk += 4) {
        ulonglong2 hA = *(const ulonglong2*)(hrA + kk);
        ulonglong2 hB = *(const ulonglong2*)(hrB + kk);
        const float* wp = wch + (kk >> 1) * 64 + cg * 4;
        ulonglong2 w0a = *(const ulonglong2*)(wp);
        ulonglong2 w1a = *(const ulonglong2*)(wp + 32);
        ulonglong2 w0b = *(const ulonglong2*)(wp + 64);
        ulonglong2 w1b = *(const ulonglong2*)(wp + 96);
        acc[0][0] = ffma2(hA.x, w0a.x, acc[0][0]);
        acc[0][1] = ffma2(hA.x, w0a.y, acc[0][1]);
        acc[0][2] = ffma2(hA.x, w1a.x, acc[0][2]);
        acc[0][3] = ffma2(hA.x, w1a.y, acc[0][3]);
        acc[1][0] = ffma2(hB.x, w0a.x, acc[1][0]);
        acc[1][1] = ffma2(hB.x, w0a.y, acc[1][1]);
        acc[1][2] = ffma2(hB.x, w1a.x, acc[1][2]);
        acc[1][3] = ffma2(hB.x, w1a.y, acc[1][3]);
        acc[0][0] = ffma2(hA.y, w0b.x, acc[0][0]);
        acc[0][1] = ffma2(hA.y, w0b.y, acc[0][1]);
        acc[0][2] = ffma2(hA.y, w1b.x, acc[0][2]);
        acc[0][3] = ffma2(hA.y, w1b.y, acc[0][3]);
        acc[1][0] = ffma2(hB.y, w0b.x, acc[1][0]);
        acc[1][1] = ffma2(hB.y, w0b.y, acc[1][1]);
        acc[1][2] = ffma2(hB.y, w1b.x, acc[1][2]);
        acc[1][3] = ffma2(hB.y, w1b.y, acc[1][3]);
      }
      if (ch == 0) {
        __syncthreads();  // chunk-0 compute done; safe to overwrite h_s
#pragma unroll
        for (int i = 0; i < 8; i++) {
          int idx = tid + NTH * i;
          int b = idx >> 7, kk = (idx & 127) << 2;
          *(float4*)(&h_s[b * HPAD + kk]) = buf[i];
        }
        __syncthreads();
      }
    }

    // ---- reduce 4 K-quarters, add xp, write gates
    if (kh > 0) {
      ull* rs = &red_s[(size_t)(tid - 128) * 8];
      *(ulonglong2*)(rs + 0) = *(ulonglong2*)(&acc[0][0]);
      *(ulonglong2*)(rs + 2) = *(ulonglong2*)(&acc[0][2]);
      *(ulonglong2*)(rs + 4) = *(ulonglong2*)(&acc[1][0]);
      *(ulonglong2*)(rs + 6) = *(ulonglong2*)(&acc[1][2]);
    }
    __syncthreads();
    if (kh == 0) {
      const ull* rs1 = &red_s[(size_t)tid * 8];
      const ull* rs2 = &red_s[(size_t)(128 + tid) * 8];
      const ull* rs3 = &red_s[(size_t)(256 + tid) * 8];
      float xa[4] = {xpA.x, xpA.y, xpA.z, xpA.w};
      float xb[4] = {xpB.x, xpB.y, xpB.z, xpB.w};
#pragma unroll
      for (int j = 0; j < 4; j++) {
        ull vA = fadd2(fadd2(acc[0][j], rs1[j]), fadd2(rs2[j], rs3[j]));
        ull vB = fadd2(fadd2(acc[1][j], rs1[4 + j]), fadd2(rs2[4 + j], rs3[4 + j]));
        gates_s[r0 * 32 + cg * 4 + j] = xa[j] + f2lo(vA) + f2hi(vA);
        gates_s[r1 * 32 + cg * 4 + j] = xb[j] + f2lo(vB) + f2hi(vB);
      }
    }
    __syncthreads();

    // ---- nonlinearity: threads 0..255 -> (b = tid>>3, u = tid&7)
    float hn = 0.0f;
    if (tid < 256) {
      const float* gr = &gates_s[b_nl * 32];
      float iv = sigm_f(gr[un]);
      float fv = sigm_f(gr[8 + un]);
      float gv = tanh_f(gr[16 + un]);
      float ov = sigm_f(gr[24 + un]);
      float cn = fv * c_s[tid] + iv * gv;
      c_s[tid] = cn;
      hn = ov * tanh_f(cn);
      g_h[1 - rb][b_nl * Uz + u0 + un] = hn;
    }

    // ---- grid-wide epoch barrier (128 CTAs all resident).
    // Arrive first; 'out' STG happens during other CTAs' arrival window.
    __syncthreads();
    if (tid == 0) {
      __threadfence();
      atomicAdd(&g_count, 1u);
    }
    if (tid < 256) out[((size_t)b_nl * Tz + t) * Uz + u0 + un] = hn;
    if (tid == 0) {
      unsigned tgt = (unsigned)(t + 1) * (unsigned)NCTA;
      volatile unsigned* vc = &g_count;
      while (*vc < tgt) {
      }
      __threadfence();
    }
    __syncthreads();
  }
}

// ---------------------------------------------------------------------------
extern "C" void kernel_launch(void* const* d_in, const int* in_sizes, int n_in,
                              void* d_out, int out_size) {
  const float* data = (const float*)d_in[0];  // [32,512,512]
  const float* Wx = (const float*)d_in[1];    // [512,4096]
  const float* Wh = (const float*)d_in[2];    // [1024,4096]
  const float* bias = (const float*)d_in[3];  // [4096]
  float* out = (float*)d_out;                 // [32,512,1024]

  const int smem_bytes =
      (Uz * 32 + Bz * HPAD + Bz * 32 + 256) * (int)sizeof(float) +
      384 * 8 * (int)sizeof(ull);
  cudaFuncSetAttribute(lstm_kernel, cudaFuncAttributeMaxDynamicSharedMemorySize,
                       smem_bytes);

  dim3 gg(Gz / 128, (Bz * Tz) / 128);
  xproj_kernel<<<gg, 256>>>(data, Wx, bias);

  lstm_kernel<<<NCTA, NTH, smem_bytes>>>(Wh, out);
}

// round 6
// speedup vs baseline: 1.6235x; 1.0915x over previous
#include <cuda_runtime.h>
#include <math.h>

#define Bz 32
#define Tz 512
#define Iz 512
#define Uz 1024
#define Gz 4096     // 4*Uz
#define NCTA 128
#define NTH 512
#define HPAD 516    // h_s row stride (floats); +16B shift per 8-row group

// Scratch (device globals: allocation-free rule)
__device__ float g_xp[(size_t)Tz * Bz * Gz];   // [T][B][4U] input projections
__device__ float g_h[2][Bz * Uz];              // double-buffered hidden state
__device__ unsigned g_count;                   // grid barrier counter

typedef unsigned long long ull;

// ---------------------------------------------------------------------------
// packed fp32x2 helpers (sm_100+): one instruction, two fp32 FMAs
// ---------------------------------------------------------------------------
__device__ __forceinline__ ull ffma2(ull a, ull b, ull c) {
  ull d;
  asm("fma.rn.f32x2 %0, %1, %2, %3;" : "=l"(d) : "l"(a), "l"(b), "l"(c));
  return d;
}
__device__ __forceinline__ ull fadd2(ull a, ull b) {
  ull d;
  asm("add.rn.f32x2 %0, %1, %2;" : "=l"(d) : "l"(a), "l"(b));
  return d;
}
__device__ __forceinline__ ull pack2(float x) {
  ull r;
  unsigned u = __float_as_uint(x);
  asm("mov.b64 %0, {%1, %1};" : "=l"(r) : "r"(u));
  return r;
}
__device__ __forceinline__ float f2lo(ull v) {
  return __uint_as_float((unsigned)v);
}
__device__ __forceinline__ float f2hi(ull v) {
  return __uint_as_float((unsigned)(v >> 32));
}
__device__ __forceinline__ float sigm_f(float x) {
  return 1.0f / (1.0f + __expf(-x));
}
__device__ __forceinline__ float tanh_f(float x) {
  return 2.0f / (1.0f + __expf(-2.0f * x)) - 1.0f;
}
// h_s row offset: 8-row groups shifted by 16B so rows 8 apart differ in banks
__device__ __forceinline__ int hoff(int r) { return r * HPAD + ((r >> 3) << 2); }

// ---------------------------------------------------------------------------
// Kernel 1: x_proj = data @ Wx + b   (M=16384, N=4096, K=512)
// 128x128 tile / 256 threads, 8x8 per thread, f32x2 over column pairs.
// Block (0,0) also resets g_h / g_count (runs before lstm in-stream).
// ---------------------------------------------------------------------------
__global__ void __launch_bounds__(256) xproj_kernel(
    const float* __restrict__ A, const float* __restrict__ W,
    const float* __restrict__ bias) {
  if (blockIdx.x == 0 && blockIdx.y == 0) {
    for (int i = threadIdx.x; i < 2 * Bz * Uz; i += 256) ((float*)g_h)[i] = 0.f;
    if (threadIdx.x == 0) g_count = 0u;
  }
  __shared__ float As[8][128];  // transposed A tile
  __shared__ float Bs[8][128];
  const int tid = threadIdx.x;
  const int m0 = blockIdx.y * 128;
  const int n0 = blockIdx.x * 128;
  const int arow = tid >> 1;
  const int acol = (tid & 1) << 2;
  const int brow = tid >> 5;
  const int bcol = (tid & 31) << 2;
  const int tr = (tid >> 4) << 3;
  const int tc = (tid & 15) << 3;

  ull accp[8][4];
#pragma unroll
  for (int i = 0; i < 8; i++)
#pragma unroll
    for (int j = 0; j < 4; j++) accp[i][j] = 0ull;

  float4 av = *(const float4*)(A + (size_t)(m0 + arow) * Iz + acol);
  float4 bv = *(const float4*)(W + (size_t)brow * Gz + n0 + bcol);

  for (int k0 = 0; k0 < Iz; k0 += 8) {
    As[acol + 0][arow] = av.x;
    As[acol + 1][arow] = av.y;
    As[acol + 2][arow] = av.z;
    As[acol + 3][arow] = av.w;
    *(float4*)(&Bs[brow][bcol]) = bv;
    __syncthreads();
    if (k0 + 8 < Iz) {
      av = *(const float4*)(A + (size_t)(m0 + arow) * Iz + k0 + 8 + acol);
      bv = *(const float4*)(W + (size_t)(k0 + 8 + brow) * Gz + n0 + bcol);
    }
#pragma unroll
    for (int kk = 0; kk < 8; kk++) {
      float4 a0 = *(const float4*)(&As[kk][tr]);
      float4 a1 = *(const float4*)(&As[kk][tr + 4]);
      ulonglong2 b0 = *(const ulonglong2*)(&Bs[kk][tc]);
      ulonglong2 b1 = *(const ulonglong2*)(&Bs[kk][tc + 4]);
      float ar[8] = {a0.x, a0.y, a0.z, a0.w, a1.x, a1.y, a1.z, a1.w};
#pragma unroll
      for (int i = 0; i < 8; i++) {
        ull aa = pack2(ar[i]);
        accp[i][0] = ffma2(aa, b0.x, accp[i][0]);
        accp[i][1] = ffma2(aa, b0.y, accp[i][1]);
        accp[i][2] = ffma2(aa, b1.x, accp[i][2]);
        accp[i][3] = ffma2(aa, b1.y, accp[i][3]);
      }
    }
    __syncthreads();
  }
#pragma unroll
  for (int i = 0; i < 8; i++) {
    int m = m0 + tr + i;  // m = b*512 + t (data is [B,T,I])
    int t = m & (Tz - 1);
    int b = m >> 9;
    float* o = &g_xp[((size_t)t * Bz + b) * Gz + n0 + tc];
#pragma unroll
    for (int j = 0; j < 4; j++) {
      o[2 * j + 0] = f2lo(accp[i][j]) + bias[n0 + tc + 2 * j + 0];
      o[2 * j + 1] = f2hi(accp[i][j]) + bias[n0 + tc + 2 * j + 1];
    }
  }
}

// ---------------------------------------------------------------------------
// Kernel 2: persistent LSTM recurrence — LDS-byte-minimized tiling.
// 128 CTAs x 512 threads. CTA: 32 rows x 32 gate-cols x K=1024.
// Thread tile: 8 rows x 4 cols x 64 ks  (R=8,C=4,Ksplit=16 -> 3 B/FFMA2).
//   tid = kh*32 + rg*8 + cgrp   (kh 0..15, rg 0..3, cgrp 0..7)
//   rows rg*8+0..7, cols cgrp*4+0..3, ks [kh*32,kh*32+32) of each 512-chunk.
// 16-way K reduction: 4-round SMEM tree, scratch aliased onto h_s.
// ---------------------------------------------------------------------------
__global__ void __launch_bounds__(NTH, 1) lstm_kernel(
    const float* __restrict__ Wh, float* __restrict__ out) {
  extern __shared__ float sm[];
  float* Wh_s = sm;                     // 32768 floats (128KB)
  float* h_s = Wh_s + Uz * 32;          // 32*HPAD+16 floats; also red scratch
  float* gates_s = h_s + Bz * HPAD + 16;  // [32][32]
  float* c_s = gates_s + Bz * 32;       // [256]
  const int tid = threadIdx.x;
  const int u0 = blockIdx.x * 8;

  // Wh_s layout per k-pair block of 64 floats (col c = gate*8+unit):
  //   dst = kpair*64 + ((c>>1)&1)*32 + (c>>2)*4 + (c&1)*2 + (k&1)
  for (int idx = tid; idx < Uz * 32; idx += NTH) {
    int k = idx >> 5, c = idx & 31;
    int dst = (k >> 1) * 64 + ((c >> 1) & 1) * 32 + (c >> 2) * 4 +
              ((c & 1) << 1) + (k & 1);
    Wh_s[dst] = Wh[(size_t)k * Gz + (c >> 3) * Uz + u0 + (c & 7)];
  }
  if (tid < 256) c_s[tid] = 0.0f;
  __syncthreads();

  const int cgrp = tid & 7;
  const int rg = (tid >> 3) & 3;
  const int kh = tid >> 5;              // 0..15
  const int lane = tid & 31;
  const int khbase = kh << 5;           // 32 ks per chunk per thread
  const int b_nl = tid >> 3, un = tid & 7;  // nonlinearity mapping (tid<256)

  for (int t = 0; t < Tz; t++) {
    const int rb = t & 1;
    const float* hg = g_h[rb];
    ull acc[8][4];
#pragma unroll
    for (int i = 0; i < 8; i++)
#pragma unroll
      for (int j = 0; j < 4; j++) acc[i][j] = 0ull;

    // xp for this thread's output cell (tid<256): 4 gate pre-act inputs
    float xpr[4];
    if (tid < 256) {
#pragma unroll
      for (int g = 0; g < 4; g++)
        xpr[g] = g_xp[((size_t)t * Bz + b_nl) * Gz + g * Uz + u0 + un];
    }

    // ---- two 512-k chunks: stage into h_s, compute
#pragma unroll 1
    for (int ch = 0; ch < 2; ch++) {
      // stage: __ldcg (L1 lines are stale across steps — other SMs wrote h)
#pragma unroll
      for (int i = 0; i < 8; i++) {
        int idx = tid + NTH * i;
        int b = idx >> 7, kk = (idx & 127) << 2;
        *(float4*)(&h_s[hoff(b) + kk]) =
            __ldcg((const float4*)(&hg[b * Uz + ch * 512 + kk]));
      }
      __syncthreads();

      const float* wch = Wh_s + ch * 256 * 64;
#pragma unroll 2
      for (int kk = khbase; kk < khbase + 32; kk += 4) {
        const float* wp = wch + (kk >> 1) * 64 + cgrp * 4;
        ulonglong2 w0a = *(const ulonglong2*)(wp);
        ulonglong2 w1a = *(const ulonglong2*)(wp + 32);
        ulonglong2 w0b = *(const ulonglong2*)(wp + 64);
        ulonglong2 w1b = *(const ulonglong2*)(wp + 96);
#pragma unroll
        for (int i = 0; i < 8; i++) {
          ulonglong2 hv = *(const ulonglong2*)(&h_s[hoff(rg * 8 + i) + kk]);
          acc[i][0] = ffma2(hv.x, w0a.x, acc[i][0]);
          acc[i][1] = ffma2(hv.x, w0a.y, acc[i][1]);
          acc[i][2] = ffma2(hv.x, w1a.x, acc[i][2]);
          acc[i][3] = ffma2(hv.x, w1a.y, acc[i][3]);
          acc[i][0] = ffma2(hv.y, w0b.x, acc[i][0]);
          acc[i][1] = ffma2(hv.y, w0b.y, acc[i][1]);
          acc[i][2] = ffma2(hv.y, w1b.x, acc[i][2]);
          acc[i][3] = ffma2(hv.y, w1b.y, acc[i][3]);
        }
      }
      __syncthreads();  // compute done before restage/reduction reuse of h_s
    }

    // ---- 16-way K reduction: 4-round tree through h_s scratch
    ulonglong2* red2 = (ulonglong2*)h_s;
#pragma unroll
    for (int m = 8; m >= 1; m >>= 1) {
      if (kh >= m && kh < 2 * m) {
        int slot = (kh - m) * 32 + lane;
#pragma unroll
        for (int i = 0; i < 8; i++) {
          red2[(i * 2 + 0) * 256 + slot] = make_ulonglong2(acc[i][0], acc[i][1]);
          red2[(i * 2 + 1) * 256 + slot] = make_ulonglong2(acc[i][2], acc[i][3]);
        }
      }
      __syncthreads();
      if (kh < m) {
        int slot = kh * 32 + lane;
#pragma unroll
        for (int i = 0; i < 8; i++) {
          ulonglong2 p0 = red2[(i * 2 + 0) * 256 + slot];
          ulonglong2 p1 = red2[(i * 2 + 1) * 256 + slot];
          acc[i][0] = fadd2(acc[i][0], p0.x);
          acc[i][1] = fadd2(acc[i][1], p0.y);
          acc[i][2] = fadd2(acc[i][2], p1.x);
          acc[i][3] = fadd2(acc[i][3], p1.y);
        }
      }
      __syncthreads();
    }

    // ---- kh0 warp (tid<32) writes gate sums (lo+hi horizontal add)
    if (tid < 32) {
#pragma unroll
      for (int i = 0; i < 8; i++) {
        float4 v;
        v.x = f2lo(acc[i][0]) + f2hi(acc[i][0]);
        v.y = f2lo(acc[i][1]) + f2hi(acc[i][1]);
        v.z = f2lo(acc[i][2]) + f2hi(acc[i][2]);
        v.w = f2lo(acc[i][3]) + f2hi(acc[i][3]);
        *(float4*)(&gates_s[(rg * 8 + i) * 32 + cgrp * 4]) = v;
      }
    }
    __syncthreads();

    // ---- nonlinearity: threads 0..255 -> (b = tid>>3, u = tid&7)
    float hn = 0.0f;
    if (tid < 256) {
      const float* gr = &gates_s[b_nl * 32];
      float iv = sigm_f(xpr[0] + gr[un]);
      float fv = sigm_f(xpr[1] + gr[8 + un]);
      float gv = tanh_f(xpr[2] + gr[16 + un]);
      float ov = sigm_f(xpr[3] + gr[24 + un]);
      float cn = fv * c_s[tid] + iv * gv;
      c_s[tid] = cn;
      hn = ov * tanh_f(cn);
      g_h[1 - rb][b_nl * Uz + u0 + un] = hn;
    }

    // ---- grid-wide epoch barrier (128 CTAs all resident).
    // Arrive first; 'out' STG happens during other CTAs' arrival window.
    __syncthreads();
    if (tid == 0) {
      __threadfence();
      atomicAdd(&g_count, 1u);
    }
    if (tid < 256) out[((size_t)b_nl * Tz + t) * Uz + u0 + un] = hn;
    if (tid == 0) {
      unsigned tgt = (unsigned)(t + 1) * (unsigned)NCTA;
      volatile unsigned* vc = &g_count;
      while (*vc < tgt) {
      }
      __threadfence();
    }
    __syncthreads();
  }
}

// ---------------------------------------------------------------------------
extern "C" void kernel_launch(void* const* d_in, const int* in_sizes, int n_in,
                              void* d_out, int out_size) {
  const float* data = (const float*)d_in[0];  // [32,512,512]
  const float* Wx = (const float*)d_in[1];    // [512,4096]
  const float* Wh = (const float*)d_in[2];    // [1024,4096]
  const float* bias = (const float*)d_in[3];  // [4096]
  float* out = (float*)d_out;                 // [32,512,1024]

  const int smem_bytes =
      (Uz * 32 + Bz * HPAD + 16 + Bz * 32 + 256) * (int)sizeof(float);
  cudaFuncSetAttribute(lstm_kernel, cudaFuncAttributeMaxDynamicSharedMemorySize,
                       smem_bytes);

  dim3 gg(Gz / 128, (Bz * Tz) / 128);
  xproj_kernel<<<gg, 256>>>(data, Wx, bias);

  lstm_kernel<<<NCTA, NTH, smem_bytes>>>(Wh, out);
}